// round 4
// baseline (speedup 1.0000x reference)
#include <cuda_runtime.h>
#include <math_constants.h>

// Problem shape (fixed for this bench instance)
#define NB   4
#define CIN  4
#define COUT 4
#define KS   5
#define PAD  2
#define HH   128
#define WW   128
#define HW   (HH*WW)

// Tiling
#define TW 32
#define TH 8
#define PW (TW + 2*PAD)   // 36
#define PH (TH + 2*PAD)   // 12

__device__ __forceinline__ float ex2_approx(float x) {
    float y;
    asm("ex2.approx.f32 %0, %1;" : "=f"(y) : "f"(x));
    return y;
}
__device__ __forceinline__ float lg2_approx(float x) {
    float y;
    asm("lg2.approx.f32 %0, %1;" : "=f"(y) : "f"(x));
    return y;
}

__global__ __launch_bounds__(256, 3)
void prop_belief_kernel(const float* __restrict__ lb,
                        const float* __restrict__ lk,
                        float* __restrict__ out)
{
    __shared__ float sh[CIN][PH][PW];   // lb * log2e, -inf padded

    const int tx = threadIdx.x;               // 0..31
    const int ty = threadIdx.y;               // 0..7
    const int x0 = blockIdx.x * TW;
    const int y0 = blockIdx.y * TH;
    const int n    = blockIdx.z >> 2;
    const int cout = blockIdx.z & 3;

    const float LOG2E = 1.4426950408889634f;
    const float LN2   = 0.6931471805599453f;

    // ---- stage lb tile (pre-scaled by log2e), pad with -inf ----
    const int tid = ty * TW + tx;
    #pragma unroll
    for (int i = tid; i < CIN * PH * PW; i += 256) {
        const int cin = i / (PH * PW);
        const int rem = i - cin * (PH * PW);
        const int r = rem / PW;
        const int c = rem - r * PW;
        const int ys = y0 - PAD + r;
        const int xs = x0 - PAD + c;
        float v = -CUDART_INF_F;
        if (ys >= 0 && ys < HH && xs >= 0 && xs < WW)
            v = __ldg(&lb[((n * CIN + cin) * HH + ys) * WW + xs]) * LOG2E;
        sh[cin][r][c] = v;
    }
    __syncthreads();

    const int yo = y0 + ty;
    const int xo = x0 + tx;

    // lk layout: [N][CIN][COUT*KK][H][W]; base at (n, cin=0, cout*KK)
    const float* lk0 = lk + ((size_t)(n * CIN) * (COUT * KS * KS)
                             + (size_t)cout * KS * KS) * HW;

    float s0 = 0.f, s1 = 0.f, s2 = 0.f, s3 = 0.f;

    #pragma unroll
    for (int ky = 0; ky < KS; ky++) {
        const int ys  = yo + PAD - ky;
        const int ysc = min(max(ys, 0), HH - 1);   // clamped address only
        const int yl  = ty + 2 * PAD - ky;         // shared row (-inf if OOB)

        // ---- phase 1: issue all 20 global loads (5 kx x 4 cin) ----
        float v[CIN * KS];
        #pragma unroll
        for (int kx = 0; kx < KS; kx++) {
            const int xs  = xo + PAD - kx;
            const int xsc = min(max(xs, 0), WW - 1);
            const int off = ysc * WW + xsc;
            const int k   = ky * KS + kx;
            #pragma unroll
            for (int cin = 0; cin < CIN; cin++) {
                v[cin * KS + kx] = __ldcs(
                    &lk0[(size_t)(cin * (COUT * KS * KS) + k) * HW + off]);
            }
        }

        // ---- phase 2: shared reads ----
        float b[CIN * KS];
        #pragma unroll
        for (int kx = 0; kx < KS; kx++) {
            const int xl = tx + 2 * PAD - kx;
            #pragma unroll
            for (int cin = 0; cin < CIN; cin++)
                b[cin * KS + kx] = sh[cin][yl][xl];
        }

        // ---- phase 3: math, 4 independent accumulator chains ----
        #pragma unroll
        for (int kx = 0; kx < KS; kx++) {
            s0 += ex2_approx(fmaf(v[0 * KS + kx], LOG2E, b[0 * KS + kx]));
            s1 += ex2_approx(fmaf(v[1 * KS + kx], LOG2E, b[1 * KS + kx]));
            s2 += ex2_approx(fmaf(v[2 * KS + kx], LOG2E, b[2 * KS + kx]));
            s3 += ex2_approx(fmaf(v[3 * KS + kx], LOG2E, b[3 * KS + kx]));
        }
    }

    const float s = (s0 + s1) + (s2 + s3);
    out[((n * COUT + cout) * HH + yo) * WW + xo] = lg2_approx(s) * LN2;
}

extern "C" void kernel_launch(void* const* d_in, const int* in_sizes, int n_in,
                              void* d_out, int out_size)
{
    const float* lb = (const float*)d_in[0];   // (4,4,128,128)
    const float* lk = (const float*)d_in[1];   // (4,4,100,128,128)
    float* out = (float*)d_out;                // (4,4,128,128)

    dim3 block(TW, TH);                        // 256 threads
    dim3 grid(WW / TW, HH / TH, NB * COUT);    // (4, 16, 16)
    prop_belief_kernel<<<grid, block>>>(lb, lk, out);
}

// round 5
// speedup vs baseline: 1.0048x; 1.0048x over previous
#include <cuda_runtime.h>
#include <math_constants.h>

// Problem shape (fixed for this bench instance)
#define NB   4
#define CIN  4
#define COUT 4
#define KS   5
#define PAD  2
#define HH   128
#define WW   128
#define HW   (HH*WW)
#define KK   (KS*KS)

// Tiling
#define TW 32
#define TH 8
#define PW (TW + 2*PAD)   // 36
#define PH (TH + 2*PAD)   // 12

__device__ __forceinline__ float ex2_approx(float x) {
    float y;
    asm("ex2.approx.f32 %0, %1;" : "=f"(y) : "f"(x));
    return y;
}
__device__ __forceinline__ float lg2_approx(float x) {
    float y;
    asm("lg2.approx.f32 %0, %1;" : "=f"(y) : "f"(x));
    return y;
}

__global__ __launch_bounds__(256, 6)
void prop_belief_kernel(const float* __restrict__ lb,
                        const float* __restrict__ lk,
                        float* __restrict__ out)
{
    __shared__ float sh[CIN][PH][PW];   // lb * log2e, -inf padded

    const int tx = threadIdx.x;               // 0..31
    const int ty = threadIdx.y;               // 0..7
    const int x0 = blockIdx.x * TW;
    const int y0 = blockIdx.y * TH;
    const int n    = blockIdx.z >> 2;
    const int cout = blockIdx.z & 3;

    const float LOG2E = 1.4426950408889634f;
    const float LN2   = 0.6931471805599453f;

    // ---- stage lb tile (pre-scaled by log2e), pad with -inf ----
    const int tid = ty * TW + tx;
    #pragma unroll
    for (int i = tid; i < CIN * PH * PW; i += 256) {
        const int cin = i / (PH * PW);
        const int rem = i - cin * (PH * PW);
        const int r = rem / PW;
        const int c = rem - r * PW;
        const int ys = y0 - PAD + r;
        const int xs = x0 - PAD + c;
        float v = -CUDART_INF_F;
        if (ys >= 0 && ys < HH && xs >= 0 && xs < WW)
            v = lb[((n * CIN + cin) * HH + ys) * WW + xs] * LOG2E;
        sh[cin][r][c] = v;
    }
    __syncthreads();

    const int yo = y0 + ty;
    const int xo = x0 + tx;

    // lk layout: [N][CIN][COUT*KK][H][W]; base at (n, cin=0, cout*KK)
    const float* lk0 = lk + ((size_t)(n * CIN) * (COUT * KK)
                             + (size_t)cout * KK) * HW;

    float s0 = 0.f, s1 = 0.f, s2 = 0.f, s3 = 0.f;

    // Depth-2 software pipeline over the 25 taps: prefetch tap k+1's
    // 4 cin-loads while doing tap k's math. Keeps 4-8 LDGs in flight
    // per thread without blowing the register budget.
    float v[2][CIN];

    // Prologue: load tap 0
    {
        const int ysc = min(max(yo + PAD - 0, 0), HH - 1);
        const int xsc = min(max(xo + PAD - 0, 0), WW - 1);
        const int off = ysc * WW + xsc;
        #pragma unroll
        for (int cin = 0; cin < CIN; cin++)
            v[0][cin] = lk0[(size_t)(cin * (COUT * KK) + 0) * HW + off];
    }

    #pragma unroll
    for (int k = 0; k < KK; k++) {
        const int cur = k & 1;
        // prefetch tap k+1
        if (k + 1 < KK) {
            const int ky1 = (k + 1) / KS;
            const int kx1 = (k + 1) % KS;
            const int ysc = min(max(yo + PAD - ky1, 0), HH - 1);
            const int xsc = min(max(xo + PAD - kx1, 0), WW - 1);
            const int off = ysc * WW + xsc;
            #pragma unroll
            for (int cin = 0; cin < CIN; cin++)
                v[cur ^ 1][cin] =
                    lk0[(size_t)(cin * (COUT * KK) + (k + 1)) * HW + off];
        }
        // math for tap k (shared reads are cheap: broadcast-free pattern)
        const int ky = k / KS;
        const int kx = k % KS;
        const int yl = ty + 2 * PAD - ky;
        const int xl = tx + 2 * PAD - kx;
        s0 += ex2_approx(fmaf(v[cur][0], LOG2E, sh[0][yl][xl]));
        s1 += ex2_approx(fmaf(v[cur][1], LOG2E, sh[1][yl][xl]));
        s2 += ex2_approx(fmaf(v[cur][2], LOG2E, sh[2][yl][xl]));
        s3 += ex2_approx(fmaf(v[cur][3], LOG2E, sh[3][yl][xl]));
    }

    const float s = (s0 + s1) + (s2 + s3);
    out[((n * COUT + cout) * HH + yo) * WW + xo] = lg2_approx(s) * LN2;
}

extern "C" void kernel_launch(void* const* d_in, const int* in_sizes, int n_in,
                              void* d_out, int out_size)
{
    const float* lb = (const float*)d_in[0];   // (4,4,128,128)
    const float* lk = (const float*)d_in[1];   // (4,4,100,128,128)
    float* out = (float*)d_out;                // (4,4,128,128)

    dim3 block(TW, TH);                        // 256 threads
    dim3 grid(WW / TW, HH / TH, NB * COUT);    // (4, 16, 16)
    prop_belief_kernel<<<grid, block>>>(lb, lk, out);
}

// round 8
// speedup vs baseline: 1.0857x; 1.0805x over previous
#include <cuda_runtime.h>
#include <math_constants.h>

#define NB   4
#define CIN  4
#define COUT 4
#define KS   5
#define KK   (KS*KS)
#define HH   128
#define WW   128
#define HW   (HH*WW)

#define TH    2           // output rows per block (1 per warp)
#define SROWS (TH + 4)    // staged lb rows incl. y-halo

__device__ __forceinline__ float ex2_approx(float x) {
    float y;
    asm("ex2.approx.f32 %0, %1;" : "=f"(y) : "f"(x));
    return y;
}
__device__ __forceinline__ float lg2_approx(float x) {
    float y;
    asm("lg2.approx.f32 %0, %1;" : "=f"(y) : "f"(x));
    return y;
}

__global__ __launch_bounds__(64)
void prop_belief_kernel(const float* __restrict__ lb,
                        const float* __restrict__ lk,
                        float* __restrict__ out)
{
    __shared__ __align__(16) float sh[CIN][SROWS][WW];  // lb*log2e, -inf rows for OOB y

    const int lane = threadIdx.x & 31;
    const int wy   = threadIdx.x >> 5;        // 0..1: row within block
    const int y0   = blockIdx.x * TH;
    const int n    = blockIdx.y >> 2;
    const int cout = blockIdx.y & 3;

    const float LOG2E = 1.4426950408889634f;
    const float LN2   = 0.6931471805599453f;

    // ---- stage lb rows [y0-2, y0+TH+1], aligned float4, no x-halo ----
    for (int i = threadIdx.x; i < CIN * SROWS * (WW / 4); i += 64) {
        const int cin = i / (SROWS * (WW / 4));
        const int rem = i - cin * (SROWS * (WW / 4));
        const int r   = rem / (WW / 4);
        const int c4  = rem - r * (WW / 4);
        const int ys  = y0 - 2 + r;
        float4 v = make_float4(-CUDART_INF_F, -CUDART_INF_F,
                               -CUDART_INF_F, -CUDART_INF_F);
        if (ys >= 0 && ys < HH) {
            const float4 t = *(const float4*)&lb[((n * CIN + cin) * HH + ys) * WW + 4 * c4];
            v = make_float4(t.x * LOG2E, t.y * LOG2E, t.z * LOG2E, t.w * LOG2E);
        }
        *(float4*)&sh[cin][r][4 * c4] = v;
    }
    __syncthreads();

    const int yo = y0 + wy;

    // lk layout: [N][CIN][COUT*KK][H][W]; base at (n, cin=0, cout*KK), this lane's 4 cols
    const float* lkbase = lk + ((size_t)(n * CIN) * (COUT * KK)
                                + (size_t)cout * KK) * HW + 4 * lane;

    // Per-kx accumulators over ALIGNED source columns; x-shift applied at the end.
    float A[KS][4];
    #pragma unroll
    for (int kx = 0; kx < KS; kx++)
        A[kx][0] = A[kx][1] = A[kx][2] = A[kx][3] = 0.f;

    #pragma unroll
    for (int ky = 0; ky < KS; ky++) {
        const int ys  = yo + 2 - ky;
        const int ysc = min(max(ys, 0), HH - 1);     // address clamp; -inf lb kills OOB
        const int r   = wy + 4 - ky;                 // staged lb row
        const int rowoff = ysc * WW;

        #pragma unroll
        for (int cin = 0; cin < CIN; cin++) {
            const float4 b4 = *(const float4*)&sh[cin][r][4 * lane];
            const float* p = lkbase + ((size_t)cin * (COUT * KK)
                                       + (size_t)ky * KS) * HW + rowoff;
            // batch the 5 kx loads: 5 LDG.128 in flight (free regs at 64-thread CTA)
            float4 v[KS];
            #pragma unroll
            for (int kx = 0; kx < KS; kx++)
                v[kx] = __ldg((const float4*)(p + (size_t)kx * HW));
            #pragma unroll
            for (int kx = 0; kx < KS; kx++) {
                A[kx][0] += ex2_approx(fmaf(v[kx].x, LOG2E, b4.x));
                A[kx][1] += ex2_approx(fmaf(v[kx].y, LOG2E, b4.y));
                A[kx][2] += ex2_approx(fmaf(v[kx].z, LOG2E, b4.z));
                A[kx][3] += ex2_approx(fmaf(v[kx].w, LOG2E, b4.w));
            }
        }
    }

    // ---- combine: out[X] = sum_kx A[kx] at source element X + 2 - kx ----
    const unsigned full = 0xFFFFFFFFu;
    float o0 = A[2][0], o1 = A[2][1], o2 = A[2][2], o3 = A[2][3];   // kx=2, shift 0
    {   // kx=1, shift +1
        float n0 = __shfl_down_sync(full, A[1][0], 1);
        if (lane == 31) n0 = 0.f;
        o0 += A[1][1]; o1 += A[1][2]; o2 += A[1][3]; o3 += n0;
    }
    {   // kx=0, shift +2
        float n0 = __shfl_down_sync(full, A[0][0], 1);
        float n1 = __shfl_down_sync(full, A[0][1], 1);
        if (lane == 31) { n0 = 0.f; n1 = 0.f; }
        o0 += A[0][2]; o1 += A[0][3]; o2 += n0; o3 += n1;
    }
    {   // kx=3, shift -1
        float p3 = __shfl_up_sync(full, A[3][3], 1);
        if (lane == 0) p3 = 0.f;
        o0 += p3; o1 += A[3][0]; o2 += A[3][1]; o3 += A[3][2];
    }
    {   // kx=4, shift -2
        float p2 = __shfl_up_sync(full, A[4][2], 1);
        float p3 = __shfl_up_sync(full, A[4][3], 1);
        if (lane == 0) { p2 = 0.f; p3 = 0.f; }
        o0 += p2; o1 += p3; o2 += A[4][0]; o3 += A[4][1];
    }

    float4 res;
    res.x = lg2_approx(o0) * LN2;
    res.y = lg2_approx(o1) * LN2;
    res.z = lg2_approx(o2) * LN2;
    res.w = lg2_approx(o3) * LN2;
    *(float4*)&out[((n * COUT + cout) * HH + yo) * WW + 4 * lane] = res;
}

extern "C" void kernel_launch(void* const* d_in, const int* in_sizes, int n_in,
                              void* d_out, int out_size)
{
    const float* lb = (const float*)d_in[0];   // (4,4,128,128)
    const float* lk = (const float*)d_in[1];   // (4,4,100,128,128)
    float* out = (float*)d_out;                // (4,4,128,128)

    dim3 block(64);                            // 2 warps = 2 output rows
    dim3 grid(HH / TH, NB * COUT);             // (64, 16) = 1024 CTAs
    prop_belief_kernel<<<grid, block>>>(lb, lk, out);
}